// round 1
// baseline (speedup 1.0000x reference)
#include <cuda_runtime.h>
#include <cstdint>

// Problem constants
#define BB 16
#define DIM 64
#define KNUM 4
#define HH 256
#define WW 256
#define KS 5
#define HO 127
#define WO 127
#define OUT_OFS (BB*DIM*HO*WO)   // 16,516,096 ; w_ret follows

// Scratch (device globals; no allocation allowed)
__device__ float g_pooled[BB*DIM];
__device__ float g_att[BB*KNUM];
__device__ float g_aggw[BB*DIM*DIM*KS*KS];   // [b][ic][oc][s] contiguous per (b,ic)

// ---------------- K1: global average pool ----------------
__global__ void pool_kernel(const float* __restrict__ x) {
    int bc = blockIdx.x;                       // b*DIM + c
    const float* p = x + (size_t)bc * (HH*WW);
    float s = 0.f;
    for (int i = threadIdx.x; i < HH*WW; i += 256) s += p[i];
    __shared__ float red[256];
    red[threadIdx.x] = s;
    __syncthreads();
    for (int off = 128; off > 0; off >>= 1) {
        if (threadIdx.x < off) red[threadIdx.x] += red[threadIdx.x + off];
        __syncthreads();
    }
    if (threadIdx.x == 0) g_pooled[bc] = red[0] * (1.f / (HH*WW));
}

// ---------------- K2: attention (fc1 -> relu -> fc2 -> softmax) ----------------
__global__ void att_kernel(const float* __restrict__ fc1_w, const float* __restrict__ fc1_b,
                           const float* __restrict__ fc2_w, const float* __restrict__ fc2_b) {
    int tid = threadIdx.x;                // 64 threads
    int b = tid >> 2, k = tid & 3;
    __shared__ float a_s[BB][KNUM];
    __shared__ float l_s[BB][KNUM];
    float acc = fc1_b[k];
    #pragma unroll 8
    for (int c = 0; c < DIM; c++) acc += g_pooled[b*DIM + c] * fc1_w[k*DIM + c];
    a_s[b][k] = fmaxf(acc, 0.f);
    __syncthreads();
    float l = fc2_b[k];
    #pragma unroll
    for (int j = 0; j < KNUM; j++) l += a_s[b][j] * fc2_w[k*KNUM + j];
    l_s[b][k] = l;
    __syncthreads();
    float m = l_s[b][0];
    #pragma unroll
    for (int j = 1; j < KNUM; j++) m = fmaxf(m, l_s[b][j]);
    float den = 0.f;
    #pragma unroll
    for (int j = 0; j < KNUM; j++) den += expf(l_s[b][j] - m);
    g_att[b*KNUM + k] = expf(l - m) / den;
}

// ---------------- K3: aggregate weights + write w_ret ----------------
__global__ void agg_kernel(const float* __restrict__ weight, float* __restrict__ out) {
    int idx = blockIdx.x * 256 + threadIdx.x;
    if (idx >= BB*DIM*DIM*KS*KS) return;
    int s = idx % 25;
    int i = (idx / 25) & 63;
    int o = (idx / (25*64)) & 63;
    int b = idx / (25*64*64);
    float v = 0.f;
    #pragma unroll
    for (int k = 0; k < KNUM; k++)
        v += g_att[b*KNUM + k] * weight[(((size_t)k*64 + o)*64 + i)*25 + s];
    g_aggw[(((size_t)b*64 + i)*64 + o)*25 + s] = v;                 // conv layout [b][ic][oc][s]
    out[OUT_OFS + (((size_t)b*64 + o)*25 + s)*64 + i] = v;          // w_ret (B*Cout, 25, Cin)
}

// ---------------- K4: per-sample conv, f32x2-packed direct conv ----------------
// Block: 256 threads = 8 warps. Each warp = 8 output channels (cg*8..+7).
// Warp lanes: tx = lane&3 (x interleave: pixels tx, tx+4, tx+8, tx+12), ty = lane>>2
// (y blocked: rows 2ty, 2ty+1). Tile = 16x16 output pixels, all 64 out channels.
// Input tile in smem as x-parity planes (row stride 19 -> conflict-free).
#define PLROWS 35
#define PLSTR  19

__global__ __launch_bounds__(256, 1)
void conv_kernel(const float* __restrict__ x, const float* __restrict__ bias,
                 float* __restrict__ out) {
    __shared__ __align__(16) float s_in[2][PLROWS][PLSTR];
    __shared__ __align__(16) float s_w[25*64];    // [s][o], o contiguous for float2 loads
    __shared__ float s_b[64];

    const int b  = blockIdx.z;
    const int bx = blockIdx.x, by = blockIdx.y;
    const int tid = threadIdx.x;
    const int cg = tid >> 5;
    const int lane = tid & 31;
    const int tx = lane & 3;
    const int ty = lane >> 2;

    // per-block recompute of aggregated bias
    if (tid < 64) {
        float v = 0.f;
        #pragma unroll
        for (int k = 0; k < KNUM; k++) v += g_att[b*KNUM + k] * bias[k*64 + tid];
        s_b[tid] = v;
    }

    unsigned long long acc[2][4][4];   // [py][px][opair] f32x2
    #pragma unroll
    for (int py = 0; py < 2; py++)
        #pragma unroll
        for (int px = 0; px < 4; px++)
            #pragma unroll
            for (int op = 0; op < 4; op++)
                acc[py][px][op] = 0ull;

    const float* xb = x + (size_t)b * DIM * HH * WW;
    const int x0 = bx * 32 - 1;        // input tile origin (global)
    const int y0 = by * 32 - 1;

    for (int ic = 0; ic < DIM; ic++) {
        // ---- load input tile 35x35 into parity planes ----
        const float* xp = xb + (size_t)ic * (HH*WW);
        for (int idx = tid; idx < 35*35; idx += 256) {
            int r = idx / 35, c = idx % 35;
            int gy = y0 + r, gx = x0 + c;
            float v = 0.f;
            if (gy >= 0 && gy < HH && gx >= 0 && gx < WW) v = __ldg(xp + (size_t)gy*WW + gx);
            s_in[c & 1][r][c >> 1] = v;
        }
        // ---- load aggregated weights for this ic: [oc][s] -> s_w[s*64+oc] ----
        const float* wp = g_aggw + (size_t)(b*64 + ic) * 1600;
        for (int idx = tid; idx < 1600; idx += 256) {
            int o = idx / 25, s = idx % 25;
            s_w[s*64 + o] = wp[idx];
        }
        __syncthreads();

        // ---- compute ----
        #pragma unroll
        for (int ky = 0; ky < 5; ky++) {
            // hoist weights for this ky: 5 kx x 4 f32x2 pairs
            unsigned long long w2[5][4];
            #pragma unroll
            for (int kx = 0; kx < 5; kx++)
                #pragma unroll
                for (int op = 0; op < 4; op++)
                    w2[kx][op] = *(const unsigned long long*)&s_w[(ky*5 + kx)*64 + cg*8 + op*2];
            #pragma unroll
            for (int py = 0; py < 2; py++) {
                const int row = 4*ty + 2*py + ky;
                float ve[4][3], vo[4][2];
                #pragma unroll
                for (int px = 0; px < 4; px++) {
                    const int cb = tx + 4*px;
                    ve[px][0] = s_in[0][row][cb];
                    ve[px][1] = s_in[0][row][cb + 1];
                    ve[px][2] = s_in[0][row][cb + 2];
                    vo[px][0] = s_in[1][row][cb];
                    vo[px][1] = s_in[1][row][cb + 1];
                }
                #pragma unroll
                for (int kx = 0; kx < 5; kx++) {
                    #pragma unroll
                    for (int px = 0; px < 4; px++) {
                        float v = (kx & 1) ? vo[px][kx >> 1] : ve[px][kx >> 1];
                        unsigned long long v2;
                        asm("mov.b64 %0, {%1, %1};" : "=l"(v2) : "f"(v));
                        #pragma unroll
                        for (int op = 0; op < 4; op++) {
                            asm("fma.rn.f32x2 %0, %1, %2, %0;"
                                : "+l"(acc[py][px][op]) : "l"(v2), "l"(w2[kx][op]));
                        }
                    }
                }
            }
        }
        __syncthreads();
    }

    // ---- writeout: out[b][o][oy][ox] + bias ----
    #pragma unroll
    for (int op = 0; op < 4; op++) {
        const int o0 = cg*8 + op*2;
        const float b0 = s_b[o0], b1 = s_b[o0 + 1];
        #pragma unroll
        for (int py = 0; py < 2; py++) {
            const int oy = by*16 + 2*ty + py;
            #pragma unroll
            for (int px = 0; px < 4; px++) {
                const int ox = bx*16 + tx + 4*px;
                if (oy < HO && ox < WO) {
                    float lo, hi;
                    asm("mov.b64 {%0, %1}, %2;" : "=f"(lo), "=f"(hi) : "l"(acc[py][px][op]));
                    size_t base = ((size_t)(b*64 + o0)) * (HO*WO) + (size_t)oy*WO + ox;
                    out[base] = lo + b0;
                    out[base + (size_t)(HO*WO)] = hi + b1;
                }
            }
        }
    }
}

extern "C" void kernel_launch(void* const* d_in, const int* in_sizes, int n_in,
                              void* d_out, int out_size) {
    const float* x      = (const float*)d_in[0];
    const float* fc1_w  = (const float*)d_in[1];
    const float* fc1_b  = (const float*)d_in[2];
    const float* fc2_w  = (const float*)d_in[3];
    const float* fc2_b  = (const float*)d_in[4];
    const float* weight = (const float*)d_in[5];
    const float* bias   = (const float*)d_in[6];
    float* out = (float*)d_out;

    pool_kernel<<<BB*DIM, 256>>>(x);
    att_kernel<<<1, 64>>>(fc1_w, fc1_b, fc2_w, fc2_b);
    agg_kernel<<<(BB*DIM*DIM*KS*KS + 255)/256, 256>>>(weight, out);
    dim3 grid((WO + 15)/16, (HO + 15)/16, BB);
    conv_kernel<<<grid, 256>>>(x, bias, out);
}

// round 5
// speedup vs baseline: 3.1395x; 3.1395x over previous
#include <cuda_runtime.h>
#include <cuda_bf16.h>
#include <cstdint>

// Problem constants
#define BB 16
#define DIM 64
#define KNUM 4
#define HH 256
#define WW 256
#define KS 5
#define HO 127
#define WO 127
#define NPIX (HO*WO)             // 16129
#define OUT_OFS (BB*DIM*HO*WO)

// ---------------- device scratch ----------------
__device__ float g_pooled[BB*DIM];
__device__ float g_att[BB*KNUM];
// aggregated + tf32-rounded weights: [b][ic][tap(32, zero-padded)][oc(64)]
__device__ __align__(16) float g_wt[(size_t)BB*DIM*32*64];

// ---------------- K1: global average pool ----------------
__global__ void pool_kernel(const float* __restrict__ x) {
    int bc = blockIdx.x;
    const float* p = x + (size_t)bc * (HH*WW);
    float s = 0.f;
    for (int i = threadIdx.x; i < HH*WW; i += 256) s += p[i];
    __shared__ float red[256];
    red[threadIdx.x] = s;
    __syncthreads();
    for (int off = 128; off > 0; off >>= 1) {
        if (threadIdx.x < off) red[threadIdx.x] += red[threadIdx.x + off];
        __syncthreads();
    }
    if (threadIdx.x == 0) g_pooled[bc] = red[0] * (1.f / (HH*WW));
}

// ---------------- K2: attention ----------------
__global__ void att_kernel(const float* __restrict__ fc1_w, const float* __restrict__ fc1_b,
                           const float* __restrict__ fc2_w, const float* __restrict__ fc2_b) {
    int tid = threadIdx.x;
    int b = tid >> 2, k = tid & 3;
    __shared__ float a_s[BB][KNUM];
    __shared__ float l_s[BB][KNUM];
    float acc = fc1_b[k];
    #pragma unroll 8
    for (int c = 0; c < DIM; c++) acc += g_pooled[b*DIM + c] * fc1_w[k*DIM + c];
    a_s[b][k] = fmaxf(acc, 0.f);
    __syncthreads();
    float l = fc2_b[k];
    #pragma unroll
    for (int j = 0; j < KNUM; j++) l += a_s[b][j] * fc2_w[k*KNUM + j];
    l_s[b][k] = l;
    __syncthreads();
    float m = l_s[b][0];
    #pragma unroll
    for (int j = 1; j < KNUM; j++) m = fmaxf(m, l_s[b][j]);
    float den = 0.f;
    #pragma unroll
    for (int j = 0; j < KNUM; j++) den += expf(l_s[b][j] - m);
    g_att[b*KNUM + k] = expf(l - m) / den;
}

// ---------------- K3: w_ret output (fp32 exact) ----------------
__global__ void agg_kernel(const float* __restrict__ weight, float* __restrict__ out) {
    int idx = blockIdx.x * 256 + threadIdx.x;
    if (idx >= BB*DIM*DIM*KS*KS) return;
    int s = idx % 25;
    int i = (idx / 25) & 63;
    int o = (idx / (25*64)) & 63;
    int b = idx / (25*64*64);
    float v = 0.f;
    #pragma unroll
    for (int k = 0; k < KNUM; k++)
        v += g_att[b*KNUM + k] * weight[(((size_t)k*64 + o)*64 + i)*25 + s];
    out[OUT_OFS + (((size_t)b*64 + o)*25 + s)*64 + i] = v;
}

// ---------------- K3b: aggregated tf32 weights [b][ic][tap32][oc64] ----------------
__global__ void wt_fill_kernel(const float* __restrict__ weight) {
    int idx = blockIdx.x * 256 + threadIdx.x;   // BB*DIM*32*64
    int oc  = idx & 63;
    int tap = (idx >> 6) & 31;
    int ic  = (idx >> 11) & 63;
    int b   = idx >> 17;
    uint32_t bits = 0u;
    if (tap < 25) {
        float v = 0.f;
        #pragma unroll
        for (int k = 0; k < KNUM; k++)
            v += g_att[b*KNUM + k] * weight[(((size_t)k*64 + oc)*64 + ic)*25 + tap];
        asm("cvt.rna.tf32.f32 %0, %1;" : "=r"(bits) : "f"(v));
    }
    *(uint32_t*)&g_wt[idx] = bits;
}

// ---------------- K4: tf32 mma.sync implicit-GEMM conv, double-buffered ----------------
// Block 256 thr = 8 warps (4 along M x 2 along N). Tile: 8x16 = 128 px, 64 oc.
// Warp tile: 32 px x 32 oc = 2 m16-tiles x 4 n8-tiles of m16n8k8.
// K per ic = 25 taps padded to 32 = 4 k-steps; accumulate over 64 ic.
// Double-buffered smem: stage ic+1 while computing ic; one barrier per ic.
#define WSTR 68   // s_w row stride (conflict-free: 68 mod 32 = 4)

__global__ __launch_bounds__(256, 2)
void conv_mma_kernel(const float* __restrict__ x, const float* __restrict__ bias,
                     float* __restrict__ out) {
    __shared__ float s_patch[2][19*36];
    __shared__ __align__(16) float s_w[2][32*WSTR];
    __shared__ float s_bias[64];

    const int tid  = threadIdx.x;
    const int lane = tid & 31;
    const int wid  = tid >> 5;
    const int warp_m = wid & 3;
    const int warp_n = wid >> 2;
    const int g   = lane >> 2;     // groupID
    const int tig = lane & 3;      // thread-in-group

    const int b   = blockIdx.z;
    const int ox0 = blockIdx.x * 16;
    const int oy0 = blockIdx.y * 8;

    if (tid < 64) {
        float v = 0.f;
        #pragma unroll
        for (int k = 0; k < KNUM; k++) v += g_att[b*KNUM + k] * bias[k*64 + tid];
        s_bias[tid] = v;
    }

    // A-fragment tap offsets: index i = 2*kstep + half; tap = kstep*8 + half*4 + tig
    int off[8]; bool val[8];
    #pragma unroll
    for (int i = 0; i < 8; i++) {
        int tap = (i >> 1)*8 + (i & 1)*4 + tig;
        val[i] = (tap < 25);
        off[i] = val[i] ? (tap/5)*36 + (tap%5) : 0;
    }
    // A row bases per m-tile: px = warp_m*32 + mt*16 + g (+8)
    int base0[2], base1[2];
    #pragma unroll
    for (int mt = 0; mt < 2; mt++) {
        int oyy = warp_m*2 + mt;          // px >> 4
        base0[mt] = oyy*2*36 + 2*g;       // input row 2*oyy, col 2*g
        base1[mt] = base0[mt] + 16;       // px+8 -> output col +8 -> input col +16
    }

    float acc[2][4][4];
    #pragma unroll
    for (int mt = 0; mt < 2; mt++)
        #pragma unroll
        for (int nt = 0; nt < 4; nt++)
            #pragma unroll
            for (int r = 0; r < 4; r++) acc[mt][nt][r] = 0.f;

    const float* xb = x + (size_t)b * DIM * (HH*WW);
    const int iy0 = 2*oy0 - 1, ix0 = 2*ox0 - 1;

    // ---- staging helper (LDG -> tf32 cvt -> STS) ----
    auto stage = [&](int ic, int bufi) {
        const float* xp = xb + (size_t)ic * (HH*WW);
        #pragma unroll
        for (int i = tid; i < 19*35; i += 256) {
            int r = i / 35, c = i % 35;
            int gy = iy0 + r, gx = ix0 + c;
            float v = 0.f;
            if ((unsigned)gy < (unsigned)HH && (unsigned)gx < (unsigned)WW)
                v = __ldg(xp + gy*WW + gx);
            uint32_t u;
            asm("cvt.rna.tf32.f32 %0, %1;" : "=r"(u) : "f"(v));
            *(uint32_t*)&s_patch[bufi][r*36 + c] = u;
        }
        const float4* ws = (const float4*)(g_wt + ((size_t)(b*DIM + ic) << 11));
        #pragma unroll
        for (int i = tid; i < 512; i += 256) {
            float4 f4 = ws[i];
            int tap = i >> 4, oc4 = (i & 15) * 4;
            *(float4*)&s_w[bufi][tap*WSTR + oc4] = f4;
        }
    };

    stage(0, 0);
    __syncthreads();

    for (int ic = 0; ic < DIM; ic++) {
        const int cur = ic & 1;
        // prefetch next ic into the other buffer (overlaps with MMAs below)
        if (ic + 1 < DIM) stage(ic + 1, cur ^ 1);

        // ---- 4 k-steps x 8 mma from buffer `cur` ----
        #pragma unroll
        for (int k = 0; k < 4; k++) {
            const float* wr = s_w[cur] + (k*8 + tig)*WSTR + warp_n*32 + g;
            uint32_t b0[4], b1[4];
            #pragma unroll
            for (int nt = 0; nt < 4; nt++) {
                b0[nt] = *(const uint32_t*)&wr[nt*8];
                b1[nt] = *(const uint32_t*)&wr[nt*8 + 4*WSTR];
            }
            const int i0 = 2*k, i1 = 2*k + 1;
            #pragma unroll
            for (int mt = 0; mt < 2; mt++) {
                uint32_t a0 = val[i0] ? *(const uint32_t*)&s_patch[cur][base0[mt] + off[i0]] : 0u;
                uint32_t a1 = val[i0] ? *(const uint32_t*)&s_patch[cur][base1[mt] + off[i0]] : 0u;
                uint32_t a2 = val[i1] ? *(const uint32_t*)&s_patch[cur][base0[mt] + off[i1]] : 0u;
                uint32_t a3 = val[i1] ? *(const uint32_t*)&s_patch[cur][base1[mt] + off[i1]] : 0u;
                #pragma unroll
                for (int nt = 0; nt < 4; nt++) {
                    asm volatile(
                        "mma.sync.aligned.m16n8k8.row.col.f32.tf32.tf32.f32 "
                        "{%0,%1,%2,%3}, {%4,%5,%6,%7}, {%8,%9}, {%0,%1,%2,%3};"
                        : "+f"(acc[mt][nt][0]), "+f"(acc[mt][nt][1]),
                          "+f"(acc[mt][nt][2]), "+f"(acc[mt][nt][3])
                        : "r"(a0), "r"(a1), "r"(a2), "r"(a3), "r"(b0[nt]), "r"(b1[nt]));
                }
            }
        }
        __syncthreads();   // staged (ic+1) visible; buffer cur free for ic+2
    }

    // ---- writeout ----
    #pragma unroll
    for (int mt = 0; mt < 2; mt++) {
        const int r = warp_m*32 + mt*16 + g;
        #pragma unroll
        for (int nt = 0; nt < 4; nt++) {
            const int oc = warp_n*32 + nt*8 + 2*tig;
            const float bz0 = s_bias[oc], bz1 = s_bias[oc + 1];
            #pragma unroll
            for (int h = 0; h < 2; h++) {        // row r (c0,c1) and r+8 (c2,c3)
                const int rr = r + h*8;
                const int oy = oy0 + (rr >> 4);
                const int ox = ox0 + (rr & 15);
                if (oy < HO && ox < WO) {
                    size_t o_idx = ((size_t)(b*64 + oc))*NPIX + (size_t)oy*WO + ox;
                    out[o_idx]        = acc[mt][nt][2*h]     + bz0;
                    out[o_idx + NPIX] = acc[mt][nt][2*h + 1] + bz1;
                }
            }
        }
    }
}

extern "C" void kernel_launch(void* const* d_in, const int* in_sizes, int n_in,
                              void* d_out, int out_size) {
    const float* x      = (const float*)d_in[0];
    const float* fc1_w  = (const float*)d_in[1];
    const float* fc1_b  = (const float*)d_in[2];
    const float* fc2_w  = (const float*)d_in[3];
    const float* fc2_b  = (const float*)d_in[4];
    const float* weight = (const float*)d_in[5];
    const float* bias   = (const float*)d_in[6];
    float* out = (float*)d_out;

    pool_kernel<<<BB*DIM, 256>>>(x);
    att_kernel<<<1, 64>>>(fc1_w, fc1_b, fc2_w, fc2_b);
    wt_fill_kernel<<<(BB*DIM*32*64)/256, 256>>>(weight);
    agg_kernel<<<(BB*DIM*DIM*KS*KS + 255)/256, 256>>>(weight, out);
    dim3 grid((WO + 15)/16, (HO + 7)/8, BB);
    conv_mma_kernel<<<grid, 256>>>(x, bias, out);
}

// round 6
// speedup vs baseline: 4.3843x; 1.3965x over previous
#include <cuda_runtime.h>
#include <cuda_bf16.h>
#include <cstdint>

// Problem constants
#define BB 16
#define DIM 64
#define KNUM 4
#define HH 256
#define WW 256
#define KS 5
#define HO 127
#define WO 127
#define NPIX (HO*WO)             // 16129
#define OUT_OFS (BB*DIM*HO*WO)

// ---------------- device scratch ----------------
__device__ float g_pooled[BB*DIM];
__device__ float g_att[BB*KNUM];
// aggregated + tf32-rounded weights, paired-tap layout:
// [b][ic][kt(16 = k*4+tig)][oc(64)][h(2)]  where tap = (kt>>2)*8 + (kt&3) + 4*h
__device__ __align__(16) float g_wt[(size_t)BB*DIM*32*64];

__device__ __forceinline__ uint32_t smem_u32(const void* p) {
    uint32_t a;
    asm("{ .reg .u64 t; cvta.to.shared.u64 t, %1; cvt.u32.u64 %0, t; }" : "=r"(a) : "l"(p));
    return a;
}
__device__ __forceinline__ void cp_async4(uint32_t dst, const void* src, int src_sz) {
    asm volatile("cp.async.ca.shared.global [%0], [%1], 4, %2;"
                 :: "r"(dst), "l"(src), "r"(src_sz) : "memory");
}
__device__ __forceinline__ void cp_async16(uint32_t dst, const void* src) {
    asm volatile("cp.async.cg.shared.global [%0], [%1], 16;"
                 :: "r"(dst), "l"(src) : "memory");
}
__device__ __forceinline__ uint32_t cvt_tf32(uint32_t v) {
    uint32_t o;
    asm("cvt.rna.tf32.f32 %0, %1;" : "=r"(o) : "f"(__uint_as_float(v)));
    return o;
}

// ---------------- K1: global average pool ----------------
__global__ void pool_kernel(const float* __restrict__ x) {
    int bc = blockIdx.x;
    const float* p = x + (size_t)bc * (HH*WW);
    float s = 0.f;
    for (int i = threadIdx.x; i < HH*WW; i += 256) s += p[i];
    __shared__ float red[256];
    red[threadIdx.x] = s;
    __syncthreads();
    for (int off = 128; off > 0; off >>= 1) {
        if (threadIdx.x < off) red[threadIdx.x] += red[threadIdx.x + off];
        __syncthreads();
    }
    if (threadIdx.x == 0) g_pooled[bc] = red[0] * (1.f / (HH*WW));
}

// ---------------- K2: attention ----------------
__global__ void att_kernel(const float* __restrict__ fc1_w, const float* __restrict__ fc1_b,
                           const float* __restrict__ fc2_w, const float* __restrict__ fc2_b) {
    int tid = threadIdx.x;
    int b = tid >> 2, k = tid & 3;
    __shared__ float a_s[BB][KNUM];
    __shared__ float l_s[BB][KNUM];
    float acc = fc1_b[k];
    #pragma unroll 8
    for (int c = 0; c < DIM; c++) acc += g_pooled[b*DIM + c] * fc1_w[k*DIM + c];
    a_s[b][k] = fmaxf(acc, 0.f);
    __syncthreads();
    float l = fc2_b[k];
    #pragma unroll
    for (int j = 0; j < KNUM; j++) l += a_s[b][j] * fc2_w[k*KNUM + j];
    l_s[b][k] = l;
    __syncthreads();
    float m = l_s[b][0];
    #pragma unroll
    for (int j = 1; j < KNUM; j++) m = fmaxf(m, l_s[b][j]);
    float den = 0.f;
    #pragma unroll
    for (int j = 0; j < KNUM; j++) den += expf(l_s[b][j] - m);
    g_att[b*KNUM + k] = expf(l - m) / den;
}

// ---------------- K3: w_ret output (fp32 exact) ----------------
__global__ void agg_kernel(const float* __restrict__ weight, float* __restrict__ out) {
    int idx = blockIdx.x * 256 + threadIdx.x;
    if (idx >= BB*DIM*DIM*KS*KS) return;
    int s = idx % 25;
    int i = (idx / 25) & 63;
    int o = (idx / (25*64)) & 63;
    int b = idx / (25*64*64);
    float v = 0.f;
    #pragma unroll
    for (int k = 0; k < KNUM; k++)
        v += g_att[b*KNUM + k] * weight[(((size_t)k*64 + o)*64 + i)*25 + s];
    out[OUT_OFS + (((size_t)b*64 + o)*25 + s)*64 + i] = v;
}

// ---------------- K3b: aggregated tf32 weights, paired-tap layout ----------------
__global__ void wt_fill_kernel(const float* __restrict__ weight) {
    int idx = blockIdx.x * 256 + threadIdx.x;   // BB*DIM*2048
    int h   = idx & 1;
    int oc  = (idx >> 1) & 63;
    int kt  = (idx >> 7) & 15;
    int ic  = (idx >> 11) & 63;
    int b   = idx >> 17;
    int tap = (kt >> 2)*8 + (kt & 3) + 4*h;
    uint32_t bits = 0u;
    if (tap < 25) {
        float v = 0.f;
        #pragma unroll
        for (int k = 0; k < KNUM; k++)
            v += g_att[b*KNUM + k] * weight[(((size_t)k*64 + oc)*64 + ic)*25 + tap];
        asm("cvt.rna.tf32.f32 %0, %1;" : "=r"(bits) : "f"(v));
    }
    *(uint32_t*)&g_wt[idx] = bits;
}

// ---------------- K4: tf32 mma.sync implicit-GEMM conv, cp.async pipelined ----------------
// Block 256 thr = 8 warps (4 along M x 2 along N). Tile: 8x16 = 128 px, 64 oc.
// Warp tile: 32 px x 32 oc = 2 m16 x 4 n8 tiles of m16n8k8.
// Double-buffered cp.async staging; halo zero-fill via src_size=0.
#define PSTR 36
#define PBUF (19*PSTR)          // 684 floats per patch buffer
#define WKT  132                // s_w kt-row stride in floats (16B-aligned, low conflict)
#define WBUF (16*WKT)           // 2112 floats per weight buffer

__global__ __launch_bounds__(256, 2)
void conv_mma_kernel(const float* __restrict__ x, const float* __restrict__ bias,
                     float* __restrict__ out) {
    __shared__ __align__(16) float s_patch[2][PBUF];
    __shared__ __align__(16) float s_w[2][WBUF];
    __shared__ float s_bias[64];

    const int tid  = threadIdx.x;
    const int lane = tid & 31;
    const int wid  = tid >> 5;
    const int warp_m = wid & 3;
    const int warp_n = wid >> 2;
    const int g   = lane >> 2;     // groupID
    const int tig = lane & 3;      // thread-in-group

    const int b   = blockIdx.z;
    const int ox0 = blockIdx.x * 16;
    const int oy0 = blockIdx.y * 8;

    if (tid < 64) {
        float v = 0.f;
        #pragma unroll
        for (int k = 0; k < KNUM; k++) v += g_att[b*KNUM + k] * bias[k*64 + tid];
        s_bias[tid] = v;
    }

    const int iy0 = 2*oy0 - 1, ix0 = 2*ox0 - 1;
    const float* xb = x + (size_t)b * DIM * (HH*WW);

    // ---- precompute per-thread patch staging slots (fixed across ic) ----
    uint32_t p_dst[3]; int p_goff[3], p_sz[3];
    const uint32_t patch_base = smem_u32(&s_patch[0][0]);
    #pragma unroll
    for (int j = 0; j < 3; j++) {
        int i = tid + j*256;
        bool on = (i < 19*35);
        int r = i / 35, c = i % 35;
        if (!on) { r = 0; c = 35; }              // park in padding column
        int gy = iy0 + r, gx = ix0 + c;
        bool valid = on && (unsigned)gy < (unsigned)HH && (unsigned)gx < (unsigned)WW;
        p_dst[j]  = patch_base + (uint32_t)(r*PSTR + c)*4u;
        p_goff[j] = valid ? (gy*WW + gx) : 0;
        p_sz[j]   = valid ? 4 : 0;
    }
    const uint32_t w_base = smem_u32(&s_w[0][0]);

    auto stage = [&](int ic, int bufi) {
        const float* xp = xb + (size_t)ic * (HH*WW);
        #pragma unroll
        for (int j = 0; j < 3; j++)
            cp_async4(p_dst[j] + (uint32_t)bufi*(PBUF*4), xp + p_goff[j], p_sz[j]);
        const float4* ws = (const float4*)(g_wt + ((size_t)(b*DIM + ic) << 11));
        #pragma unroll
        for (int t = 0; t < 2; t++) {
            int jj = tid + t*256;               // 512 float4 total
            int kt = jj >> 5, c4 = jj & 31;
            cp_async16(w_base + (uint32_t)bufi*(WBUF*4) + (uint32_t)(kt*WKT + c4*4)*4u,
                       ws + jj);
        }
        asm volatile("cp.async.commit_group;" ::: "memory");
    };

    // A-fragment tap offsets: index i = 2*kstep + half; tap = kstep*8 + half*4 + tig
    int off[8]; bool val[8];
    #pragma unroll
    for (int i = 0; i < 8; i++) {
        int tap = (i >> 1)*8 + (i & 1)*4 + tig;
        val[i] = (tap < 25);
        off[i] = val[i] ? (tap/5)*PSTR + (tap%5) : 0;
    }
    int base0[2], base1[2];
    #pragma unroll
    for (int mt = 0; mt < 2; mt++) {
        int oyy = warp_m*2 + mt;
        base0[mt] = oyy*2*PSTR + 2*g;
        base1[mt] = base0[mt] + 16;
    }

    float acc[2][4][4];
    #pragma unroll
    for (int mt = 0; mt < 2; mt++)
        #pragma unroll
        for (int nt = 0; nt < 4; nt++)
            #pragma unroll
            for (int r = 0; r < 4; r++) acc[mt][nt][r] = 0.f;

    stage(0, 0);
    asm volatile("cp.async.wait_group 0;" ::: "memory");
    __syncthreads();

    for (int ic = 0; ic < DIM; ic++) {
        const int cur = ic & 1;
        if (ic + 1 < DIM) stage(ic + 1, cur ^ 1);   // async; no stall

        #pragma unroll
        for (int k = 0; k < 4; k++) {
            // B fragments: float2 = taps (k*8+tig, k*8+tig+4) for oc column
            const float* wr = s_w[cur] + (k*4 + tig)*WKT + (warp_n*32 + g)*2;
            uint32_t b0[4], b1[4];
            #pragma unroll
            for (int nt = 0; nt < 4; nt++) {
                float2 w2 = *(const float2*)&wr[nt*16];
                b0[nt] = __float_as_uint(w2.x);
                b1[nt] = __float_as_uint(w2.y);
            }
            const int i0 = 2*k, i1 = 2*k + 1;
            #pragma unroll
            for (int mt = 0; mt < 2; mt++) {
                uint32_t a0 = val[i0] ? cvt_tf32(*(const uint32_t*)&s_patch[cur][base0[mt] + off[i0]]) : 0u;
                uint32_t a1 = val[i0] ? cvt_tf32(*(const uint32_t*)&s_patch[cur][base1[mt] + off[i0]]) : 0u;
                uint32_t a2 = val[i1] ? cvt_tf32(*(const uint32_t*)&s_patch[cur][base0[mt] + off[i1]]) : 0u;
                uint32_t a3 = val[i1] ? cvt_tf32(*(const uint32_t*)&s_patch[cur][base1[mt] + off[i1]]) : 0u;
                #pragma unroll
                for (int nt = 0; nt < 4; nt++) {
                    asm volatile(
                        "mma.sync.aligned.m16n8k8.row.col.f32.tf32.tf32.f32 "
                        "{%0,%1,%2,%3}, {%4,%5,%6,%7}, {%8,%9}, {%0,%1,%2,%3};"
                        : "+f"(acc[mt][nt][0]), "+f"(acc[mt][nt][1]),
                          "+f"(acc[mt][nt][2]), "+f"(acc[mt][nt][3])
                        : "r"(a0), "r"(a1), "r"(a2), "r"(a3), "r"(b0[nt]), "r"(b1[nt]));
                }
            }
        }
        asm volatile("cp.async.wait_group 0;" ::: "memory");
        __syncthreads();
    }

    // ---- writeout ----
    #pragma unroll
    for (int mt = 0; mt < 2; mt++) {
        const int r = warp_m*32 + mt*16 + g;
        #pragma unroll
        for (int nt = 0; nt < 4; nt++) {
            const int oc = warp_n*32 + nt*8 + 2*tig;
            const float bz0 = s_bias[oc], bz1 = s_bias[oc + 1];
            #pragma unroll
            for (int h = 0; h < 2; h++) {
                const int rr = r + h*8;
                const int oy = oy0 + (rr >> 4);
                const int ox = ox0 + (rr & 15);
                if (oy < HO && ox < WO) {
                    size_t o_idx = ((size_t)(b*64 + oc))*NPIX + (size_t)oy*WO + ox;
                    out[o_idx]        = acc[mt][nt][2*h]     + bz0;
                    out[o_idx + NPIX] = acc[mt][nt][2*h + 1] + bz1;
                }
            }
        }
    }
}

extern "C" void kernel_launch(void* const* d_in, const int* in_sizes, int n_in,
                              void* d_out, int out_size) {
    const float* x      = (const float*)d_in[0];
    const float* fc1_w  = (const float*)d_in[1];
    const float* fc1_b  = (const float*)d_in[2];
    const float* fc2_w  = (const float*)d_in[3];
    const float* fc2_b  = (const float*)d_in[4];
    const float* weight = (const float*)d_in[5];
    const float* bias   = (const float*)d_in[6];
    float* out = (float*)d_out;

    pool_kernel<<<BB*DIM, 256>>>(x);
    att_kernel<<<1, 64>>>(fc1_w, fc1_b, fc2_w, fc2_b);
    wt_fill_kernel<<<(BB*DIM*32*64)/256, 256>>>(weight);
    agg_kernel<<<(BB*DIM*DIM*KS*KS + 255)/256, 256>>>(weight, out);
    dim3 grid((WO + 15)/16, (HO + 7)/8, BB);
    conv_mma_kernel<<<grid, 256>>>(x, bias, out);
}